// round 6
// baseline (speedup 1.0000x reference)
#include <cuda_runtime.h>
#include <cstdint>

#if defined(__CUDA_ARCH__) && defined(__CUDA_ARCH_FEAT_SM103_ALL)
#define USE_TC 1
#else
#define USE_TC 0
#endif

#define TOKENS 16384
#define DM     4096
#define NE     64

// ============================================================================
// W pre-split: 3-way exact bf16 split of W -> swizzled B-tile images.
// g_wb[chunk][split][8192B], 24576B per chunk.
// ============================================================================
__device__ __align__(16) unsigned char g_wb[64 * 24576];

__device__ __forceinline__ void split8(const float4 va, const float4 vb,
                                       uint32_t* h1, uint32_t* h2, uint32_t* h3) {
    float f[8] = {va.x, va.y, va.z, va.w, vb.x, vb.y, vb.z, vb.w};
#pragma unroll
    for (int p = 0; p < 4; ++p) {
        float a = f[2 * p], c = f[2 * p + 1];
        uint32_t ua = __float_as_uint(a), uc = __float_as_uint(c);
        h1[p] = __byte_perm(ua, uc, 0x7632);
        float r1a = a - __uint_as_float(ua & 0xffff0000u);
        float r1c = c - __uint_as_float(uc & 0xffff0000u);
        uint32_t ra = __float_as_uint(r1a), rc = __float_as_uint(r1c);
        h2[p] = __byte_perm(ra, rc, 0x7632);
        float r2a = r1a - __uint_as_float(ra & 0xffff0000u);
        float r2c = r1c - __uint_as_float(rc & 0xffff0000u);
        asm("cvt.rn.bf16x2.f32 %0, %1, %2;" : "=r"(h3[p]) : "f"(r2c), "f"(r2a));
    }
}

__global__ __launch_bounds__(256)
void wsplit_kernel(const float* __restrict__ W) {
    const int c = blockIdx.x >> 1;          // chunk 0..63
    const int h = blockIdx.x & 1;           // expert half
    const int t = threadIdx.x;              // 256
    const int e  = h * 32 + (t >> 3);       // expert row
    const int fg = (t & 7) * 8;             // 8 floats per thread
    const float4* src = (const float4*)(W + (size_t)e * DM + c * 64 + fg);
    unsigned char* dst = g_wb + (size_t)c * 24576;
    uint32_t h1[4], h2[4], h3[4];
    split8(src[0], src[1], h1, h2, h3);
    uint32_t off = (uint32_t)(e * 128 + fg * 2);
    uint32_t sw = off ^ ((off >> 3) & 0x70);
    *(uint4*)(dst + sw)         = make_uint4(h1[0], h1[1], h1[2], h1[3]);
    *(uint4*)(dst + 8192 + sw)  = make_uint4(h2[0], h2[1], h2[2], h2[3]);
    *(uint4*)(dst + 16384 + sw) = make_uint4(h3[0], h3[1], h3[2], h3[3]);
}

// ============================================================================
// SIMT f32x2 fallback (active only when tcgen05 feature path absent)
// ============================================================================
#define BMF       64
#define BKF       32
#define NTHREADSF 128
#define KTILESF   (DM / BKF)

__device__ __forceinline__ unsigned long long pack2(float a, float b) {
    unsigned long long r;
    asm("mov.b64 %0, {%1, %2};" : "=l"(r) : "f"(a), "f"(b));
    return r;
}
__device__ __forceinline__ void fma2(unsigned long long& d,
                                     unsigned long long a,
                                     unsigned long long b) {
    asm("fma.rn.f32x2 %0, %1, %2, %0;" : "+l"(d) : "l"(a), "l"(b));
}
__device__ __forceinline__ float2 unpack2(unsigned long long v) {
    float2 f;
    asm("mov.b64 {%0, %1}, %2;" : "=f"(f.x), "=f"(f.y) : "l"(v));
    return f;
}

__global__ __launch_bounds__(NTHREADSF)
void router_simt(const float* __restrict__ x,
                 const float* __restrict__ W,
                 const float* __restrict__ b,
                 float* __restrict__ out) {
#if USE_TC
    return;
#else
    __shared__ float xs[BMF][37];
    __shared__ float ws[BKF][66];
    __shared__ float logits[BMF][65];
    __shared__ float bs[NE];

    const int t = threadIdx.x;
    const int tokBase = blockIdx.x * BMF;
    const int lr  = t >> 3;
    const int lkv = (t & 7) * 4;
    const int tm = t & 15;
    const int te = t >> 4;
    const int m0 = tm * 4;
    const int e0 = te * 8;

    if (t < NE) bs[t] = b[t];

    unsigned long long acc[4][4];
#pragma unroll
    for (int i = 0; i < 4; ++i)
#pragma unroll
        for (int p = 0; p < 4; ++p) acc[i][p] = 0ull;

    float4 px[4], pw[4];
#pragma unroll
    for (int p = 0; p < 4; ++p) {
        int r = lr + p * 16;
        px[p] = *(const float4*)(x + (tokBase + r) * DM + lkv);
        pw[p] = *(const float4*)(W + r * DM + lkv);
    }

    for (int it = 0; it < KTILESF; ++it) {
#pragma unroll
        for (int p = 0; p < 4; ++p) {
            int r = lr + p * 16;
            xs[r][lkv + 0] = px[p].x; xs[r][lkv + 1] = px[p].y;
            xs[r][lkv + 2] = px[p].z; xs[r][lkv + 3] = px[p].w;
            ws[lkv + 0][r] = pw[p].x; ws[lkv + 1][r] = pw[p].y;
            ws[lkv + 2][r] = pw[p].z; ws[lkv + 3][r] = pw[p].w;
        }
        __syncthreads();

        if (it + 1 < KTILESF) {
            int k0 = (it + 1) * BKF;
#pragma unroll
            for (int p = 0; p < 4; ++p) {
                int r = lr + p * 16;
                px[p] = *(const float4*)(x + (tokBase + r) * DM + k0 + lkv);
                pw[p] = *(const float4*)(W + r * DM + k0 + lkv);
            }
        }

#pragma unroll 8
        for (int kk = 0; kk < BKF; ++kk) {
            float xv0 = xs[m0 + 0][kk], xv1 = xs[m0 + 1][kk];
            float xv2 = xs[m0 + 2][kk], xv3 = xs[m0 + 3][kk];
            unsigned long long xp[4];
            xp[0] = pack2(xv0, xv0); xp[1] = pack2(xv1, xv1);
            xp[2] = pack2(xv2, xv2); xp[3] = pack2(xv3, xv3);
            const float2* wrow = (const float2*)(&ws[kk][0]);
            unsigned long long wp[4];
#pragma unroll
            for (int p = 0; p < 4; ++p) {
                float2 wv = wrow[(e0 >> 1) + p];
                wp[p] = pack2(wv.x, wv.y);
            }
#pragma unroll
            for (int i = 0; i < 4; ++i)
#pragma unroll
                for (int p = 0; p < 4; ++p) fma2(acc[i][p], xp[i], wp[p]);
        }
        __syncthreads();
    }

#pragma unroll
    for (int i = 0; i < 4; ++i)
#pragma unroll
        for (int p = 0; p < 4; ++p) {
            float2 f = unpack2(acc[i][p]);
            logits[m0 + i][e0 + 2 * p + 0] = f.x;
            logits[m0 + i][e0 + 2 * p + 1] = f.y;
        }
    __syncthreads();

    if (t < BMF) {
        int tok = tokBase + t;
        float m1 = -3.402823466e+38f, m2 = -3.402823466e+38f;
        int i1 = 0, i2 = 0;
#pragma unroll
        for (int e = 0; e < NE; ++e) {
            float v = logits[t][e] + bs[e];
            if (v > m1)      { m2 = m1; i2 = i1; m1 = v; i1 = e; }
            else if (v > m2) { m2 = v;  i2 = e; }
        }
        float sum = 0.0f;
#pragma unroll
        for (int e = 0; e < NE; ++e)
            sum = sum + __expf(logits[t][e] + bs[e] - m1);
        float inv = 1.0f / sum;
        out[tok * 2 + 0] = (float)i1;
        out[tok * 2 + 1] = (float)i2;
        out[TOKENS * 2 + tok * 2 + 0] = inv;
        out[TOKENS * 2 + tok * 2 + 1] = __expf(m2 - m1) * inv;
    }
#endif
}

// ============================================================================
// tcgen05 kernel: 3-stage ring, 2-deep x prefetch, 6 MMA products
// ============================================================================
#define BM      128
#define BK      64
#define NCHUNK  (DM / BK)
#define NPROD   512
#define NTHR    544
#define NSTAGE  3
#define A_SZ    16384
#define B_SZ    8192
#define B_OFF   49152
#define B_BYTES 24576
#define STAGE_SZ 73728
#define SMEM_TOTAL (2048 + NSTAGE * STAGE_SZ)   // 223232 B

#define IDESC 0x8100490u   // F32 acc, BF16 a/b, N=64, M=128

#define OFF_TMEM  0
#define OFF_FULL(s) (8  + (s) * 8)
#define OFF_DONE(s) (40 + (s) * 8)
#define OFF_FINAL 72
#define OFF_BIAS  128

#if USE_TC
__device__ __forceinline__ uint32_t smem_u32(const void* p) {
    uint32_t a;
    asm("{ .reg .u64 t; cvta.to.shared.u64 t, %1; cvt.u32.u64 %0, t; }" : "=r"(a) : "l"(p));
    return a;
}
__device__ __forceinline__ bool elect1() {
    uint32_t p;
    asm volatile("{ .reg .pred P; elect.sync _|P, 0xFFFFFFFF; selp.b32 %0, 1, 0, P; }" : "=r"(p));
    return p != 0;
}
#define MBAR_INIT(a, c) asm volatile("mbarrier.init.shared.b64 [%0], %1;" :: "r"(a), "r"(c) : "memory")
#define MBAR_ARRIVE(a)  asm volatile("mbarrier.arrive.shared.b64 _, [%0];" :: "r"(a) : "memory")
#define MBAR_EXPECT(a, n) asm volatile("mbarrier.arrive.expect_tx.shared.b64 _, [%0], %1;" :: "r"(a), "r"(n) : "memory")

__device__ __forceinline__ void mbar_wait(uint32_t mb, uint32_t parity) {
    uint32_t done;
    asm volatile("{ .reg .pred p;\n\t"
        "mbarrier.try_wait.parity.acquire.cta.shared::cta.b64 p, [%1], %2;\n\t"
        "selp.b32 %0, 1, 0, p; }" : "=r"(done) : "r"(mb), "r"(parity) : "memory");
    while (!done) {
        asm volatile("{ .reg .pred p;\n\t"
            "mbarrier.try_wait.parity.acquire.cta.shared::cta.b64 p, [%1], %2, 0x989680;\n\t"
            "selp.b32 %0, 1, 0, p; }" : "=r"(done) : "r"(mb), "r"(parity) : "memory");
    }
}

#define TC_ALLOC(sa, n)  asm volatile("tcgen05.alloc.cta_group::1.sync.aligned.shared::cta.b32 [%0], %1;" :: "r"(sa), "r"(n) : "memory")
#define TC_DEALLOC(t, n) asm volatile("tcgen05.dealloc.cta_group::1.sync.aligned.b32 %0, %1;" :: "r"(t), "r"(n))
#define TC_RELINQ()      asm volatile("tcgen05.relinquish_alloc_permit.cta_group::1.sync.aligned;")
#define TC_COMMIT(mb)    asm volatile("tcgen05.commit.cta_group::1.mbarrier::arrive::one.shared::cluster.b64 [%0];" :: "r"(mb) : "memory")
#define TC_FENCE_AFTER() asm volatile("tcgen05.fence::after_thread_sync;" ::: "memory")
#define TC_WAIT_LD()     asm volatile("tcgen05.wait::ld.sync.aligned;" ::: "memory")
#define FENCE_ASYNC()    asm volatile("fence.proxy.async.shared::cta;" ::: "memory")

__device__ __forceinline__ void bulk_g2s(uint32_t dst, const void* src,
                                         uint32_t bytes, uint32_t mbar) {
    asm volatile("cp.async.bulk.shared::cluster.global.mbarrier::complete_tx::bytes "
                 "[%0], [%1], %2, [%3];"
                 :: "r"(dst), "l"(src), "r"(bytes), "r"(mbar) : "memory");
}

__device__ __forceinline__ void tcmma(uint32_t d, uint64_t ad, uint64_t bd, uint32_t en) {
    asm volatile("{ .reg .pred p;\n\t"
        "setp.ne.u32 p, %4, 0;\n\t"
        "tcgen05.mma.cta_group::1.kind::f16 [%0], %1, %2, %3, {%5,%5,%5,%5}, p; }"
        :: "r"(d), "l"(ad), "l"(bd), "r"(IDESC), "r"(en), "r"(0u) : "memory");
}

#define LDTM32(r, addr) \
    asm volatile("tcgen05.ld.sync.aligned.32x32b.x32.b32 " \
        "{%0,%1,%2,%3,%4,%5,%6,%7,%8,%9,%10,%11,%12,%13,%14,%15," \
        "%16,%17,%18,%19,%20,%21,%22,%23,%24,%25,%26,%27,%28,%29,%30,%31}, [%32];" \
        : "=r"((r)[0]),"=r"((r)[1]),"=r"((r)[2]),"=r"((r)[3]),"=r"((r)[4]),"=r"((r)[5]),"=r"((r)[6]),"=r"((r)[7]), \
          "=r"((r)[8]),"=r"((r)[9]),"=r"((r)[10]),"=r"((r)[11]),"=r"((r)[12]),"=r"((r)[13]),"=r"((r)[14]),"=r"((r)[15]), \
          "=r"((r)[16]),"=r"((r)[17]),"=r"((r)[18]),"=r"((r)[19]),"=r"((r)[20]),"=r"((r)[21]),"=r"((r)[22]),"=r"((r)[23]), \
          "=r"((r)[24]),"=r"((r)[25]),"=r"((r)[26]),"=r"((r)[27]),"=r"((r)[28]),"=r"((r)[29]),"=r"((r)[30]),"=r"((r)[31]) \
        : "r"(addr))

__device__ __forceinline__ void cvt_store8(float4 va, float4 vb, uint32_t base,
                                           uint32_t sstride, uint32_t off) {
    uint32_t sw = base + (off ^ ((off >> 3) & 0x70));
    uint32_t h1[4], h2[4], h3[4];
    split8(va, vb, h1, h2, h3);
    asm volatile("st.shared.v4.b32 [%0], {%1,%2,%3,%4};"
                 :: "r"(sw), "r"(h1[0]), "r"(h1[1]), "r"(h1[2]), "r"(h1[3]));
    asm volatile("st.shared.v4.b32 [%0], {%1,%2,%3,%4};"
                 :: "r"(sw + sstride), "r"(h2[0]), "r"(h2[1]), "r"(h2[2]), "r"(h2[3]));
    asm volatile("st.shared.v4.b32 [%0], {%1,%2,%3,%4};"
                 :: "r"(sw + 2 * sstride), "r"(h3[0]), "r"(h3[1]), "r"(h3[2]), "r"(h3[3]));
}
#endif  // USE_TC

__global__ void __launch_bounds__(NTHR, 1)
router_tc(const float* __restrict__ x, const float* __restrict__ b,
          float* __restrict__ out) {
#if USE_TC
    extern __shared__ char smem[];
    const uint32_t sb = smem_u32(smem);
    const uint32_t ab = (sb + 2047) & ~1023u;
    const int t = threadIdx.x;

    if (t == 0) {
#pragma unroll
        for (int s = 0; s < NSTAGE; ++s) {
            MBAR_INIT(sb + OFF_FULL(s), 2);   // expect_tx arrive + post-bar arrive
            MBAR_INIT(sb + OFF_DONE(s), 1);
        }
        MBAR_INIT(sb + OFF_FINAL, 1);
    }
    if (t < NE) *(float*)(smem + OFF_BIAS + t * 4) = b[t];
    if (t >= NPROD) {
        TC_ALLOC(sb + OFF_TMEM, 128);
    }
    __syncthreads();
    uint32_t tmem;
    asm volatile("ld.shared.b32 %0, [%1];" : "=r"(tmem) : "r"(sb + OFF_TMEM));

    if (t >= NPROD) {
        // ---- MMA warp ----
        const uint64_t DB = (2ULL << 61) | (1ULL << 46) | (64ULL << 32) | (1ULL << 16);
        uint64_t ad[NSTAGE][3], bd[NSTAGE][3];
#pragma unroll
        for (int s = 0; s < NSTAGE; ++s)
#pragma unroll
            for (int sp = 0; sp < 3; ++sp) {
                ad[s][sp] = DB | (((ab + s * STAGE_SZ + sp * A_SZ) >> 4) & 0x3FFF);
                bd[s][sp] = DB | (((ab + s * STAGE_SZ + B_OFF + sp * B_SZ) >> 4) & 0x3FFF);
            }
        int phF[NSTAGE] = {0, 0, 0};
        int s = 0;
        for (int i = 0; i < NCHUNK; ++i) {
            mbar_wait(sb + OFF_FULL(s), phF[s]);
            phF[s] ^= 1;
            if (elect1()) {
#pragma unroll
                for (int ks = 0; ks < 4; ++ks) {
                    uint32_t en0 = (i > 0 || ks > 0) ? 1u : 0u;
                    uint64_t ko = (uint64_t)(ks * 2);
                    tcmma(tmem, ad[s][0] + ko, bd[s][0] + ko, en0);  // x1w1
                    tcmma(tmem, ad[s][0] + ko, bd[s][1] + ko, 1u);   // x1w2
                    tcmma(tmem, ad[s][1] + ko, bd[s][0] + ko, 1u);   // x2w1
                    tcmma(tmem, ad[s][1] + ko, bd[s][1] + ko, 1u);   // x2w2
                    tcmma(tmem, ad[s][0] + ko, bd[s][2] + ko, 1u);   // x1w3
                    tcmma(tmem, ad[s][2] + ko, bd[s][0] + ko, 1u);   // x3w1
                }
                TC_COMMIT(sb + OFF_DONE(s));
            }
            if (++s == NSTAGE) s = 0;
        }
        if (elect1()) TC_COMMIT(sb + OFF_FINAL);
    } else {
        // ---- producers: x conversion (2-deep prefetch) + B bulk copy ----
        const int row  = t >> 2;
        const int colf = (t & 3) * 16;
        const float* xp = x + (size_t)(blockIdx.x * BM + row) * DM + colf;
        const uint32_t aoff = (uint32_t)(row * 128 + colf * 2);

        float4 buf[2][4];
#pragma unroll
        for (int j = 0; j < 4; ++j) buf[0][j] = ((const float4*)xp)[j];
#pragma unroll
        for (int j = 0; j < 4; ++j) buf[1][j] = ((const float4*)(xp + BK))[j];

        int phD[NSTAGE] = {0, 0, 0};
        int s = 0;
        for (int i = 0; i < NCHUNK; ++i) {
            if (i >= NSTAGE) {
                mbar_wait(sb + OFF_DONE(s), phD[s]);
                phD[s] ^= 1;
            }
            const uint32_t abase = ab + s * STAGE_SZ;
            if (t == 0) {
                MBAR_EXPECT(sb + OFF_FULL(s), B_BYTES);
                bulk_g2s(abase + B_OFF, g_wb + (size_t)i * B_BYTES, B_BYTES,
                         sb + OFF_FULL(s));
            }
            const int bsl = i & 1;
            cvt_store8(buf[bsl][0], buf[bsl][1], abase, A_SZ, aoff);
            cvt_store8(buf[bsl][2], buf[bsl][3], abase, A_SZ, aoff + 16);
            if (i + 2 < NCHUNK) {
                const float4* xn = (const float4*)(xp + (i + 2) * BK);
#pragma unroll
                for (int j = 0; j < 4; ++j) buf[bsl][j] = xn[j];
            }
            FENCE_ASYNC();
            asm volatile("bar.sync 1, 512;" ::: "memory");
            if (t == 0) MBAR_ARRIVE(sb + OFF_FULL(s));
            if (++s == NSTAGE) s = 0;
        }
    }

    // ---- epilogue: warps 0-3 read TMEM, bias + top-2 + softmax ----
    if (t < 128) {
        mbar_wait(sb + OFF_FINAL, 0);
        TC_FENCE_AFTER();
        uint32_t d0[32], d1[32];
        LDTM32(d0, tmem);
        LDTM32(d1, tmem + 32);
        TC_WAIT_LD();

        float vv[64];
#pragma unroll
        for (int e = 0; e < 32; ++e)
            vv[e] = __uint_as_float(d0[e]) + *(const float*)(smem + OFF_BIAS + e * 4);
#pragma unroll
        for (int e = 0; e < 32; ++e)
            vv[32 + e] = __uint_as_float(d1[e]) + *(const float*)(smem + OFF_BIAS + (32 + e) * 4);

        float m1 = -3.402823466e38f, m2 = -3.402823466e38f;
        int i1 = 0, i2 = 0;
#pragma unroll
        for (int e = 0; e < 64; ++e) {
            float v = vv[e];
            if (v > m1)      { m2 = m1; i2 = i1; m1 = v; i1 = e; }
            else if (v > m2) { m2 = v;  i2 = e; }
        }
        float sum = 0.0f;
#pragma unroll
        for (int e = 0; e < 64; ++e) sum += __expf(vv[e] - m1);
        float inv = 1.0f / sum;

        int tok = blockIdx.x * BM + t;
        out[tok * 2 + 0] = (float)i1;
        out[tok * 2 + 1] = (float)i2;
        out[TOKENS * 2 + tok * 2 + 0] = inv;
        out[TOKENS * 2 + tok * 2 + 1] = __expf(m2 - m1) * inv;
    }

    __syncthreads();
    if (t >= NPROD) {
        TC_RELINQ();
        TC_DEALLOC(tmem, 128);
    }
#endif  // USE_TC
}

// ============================================================================
extern "C" void kernel_launch(void* const* d_in, const int* in_sizes, int n_in,
                              void* d_out, int out_size) {
    const float* x = (const float*)d_in[0];
    const float* W = (const float*)d_in[1];
    const float* b = (const float*)d_in[2];
    float* out = (float*)d_out;
    (void)in_sizes; (void)n_in; (void)out_size;

    wsplit_kernel<<<128, 256>>>(W);

    router_simt<<<TOKENS / BMF, NTHREADSF>>>(x, W, b, out);

    cudaFuncSetAttribute(router_tc, cudaFuncAttributeMaxDynamicSharedMemorySize, SMEM_TOTAL);
    router_tc<<<TOKENS / BM, NTHR, SMEM_TOTAL>>>(x, b, out);
}

// round 8
// speedup vs baseline: 2.0139x; 2.0139x over previous
#include <cuda_runtime.h>
#include <cstdint>

#if defined(__CUDA_ARCH__) && defined(__CUDA_ARCH_FEAT_SM103_ALL)
#define USE_TC 1
#else
#define USE_TC 0
#endif

#define TOKENS 16384
#define DM     4096
#define NE     64

// ============================================================================
// W pre-split: 3-way exact bf16 split of W -> swizzled B-tile images.
// g_wb[chunk][split][8192B], 24576B per chunk.
// ============================================================================
__device__ __align__(16) unsigned char g_wb[64 * 24576];

__device__ __forceinline__ void split8(const float4 va, const float4 vb,
                                       uint32_t* h1, uint32_t* h2, uint32_t* h3) {
    float f[8] = {va.x, va.y, va.z, va.w, vb.x, vb.y, vb.z, vb.w};
#pragma unroll
    for (int p = 0; p < 4; ++p) {
        float a = f[2 * p], c = f[2 * p + 1];
        uint32_t ua = __float_as_uint(a), uc = __float_as_uint(c);
        h1[p] = __byte_perm(ua, uc, 0x7632);
        float r1a = a - __uint_as_float(ua & 0xffff0000u);
        float r1c = c - __uint_as_float(uc & 0xffff0000u);
        uint32_t ra = __float_as_uint(r1a), rc = __float_as_uint(r1c);
        h2[p] = __byte_perm(ra, rc, 0x7632);
        float r2a = r1a - __uint_as_float(ra & 0xffff0000u);
        float r2c = r1c - __uint_as_float(rc & 0xffff0000u);
        asm("cvt.rn.bf16x2.f32 %0, %1, %2;" : "=r"(h3[p]) : "f"(r2c), "f"(r2a));
    }
}

__global__ __launch_bounds__(256)
void wsplit_kernel(const float* __restrict__ W) {
    const int c = blockIdx.x >> 1;          // chunk 0..63
    const int h = blockIdx.x & 1;           // expert half
    const int t = threadIdx.x;              // 256
    const int e  = h * 32 + (t >> 3);       // expert row
    const int fg = (t & 7) * 8;             // 8 floats per thread
    const float4* src = (const float4*)(W + (size_t)e * DM + c * 64 + fg);
    unsigned char* dst = g_wb + (size_t)c * 24576;
    uint32_t h1[4], h2[4], h3[4];
    split8(src[0], src[1], h1, h2, h3);
    uint32_t off = (uint32_t)(e * 128 + fg * 2);
    uint32_t sw = off ^ ((off >> 3) & 0x70);
    *(uint4*)(dst + sw)         = make_uint4(h1[0], h1[1], h1[2], h1[3]);
    *(uint4*)(dst + 8192 + sw)  = make_uint4(h2[0], h2[1], h2[2], h2[3]);
    *(uint4*)(dst + 16384 + sw) = make_uint4(h3[0], h3[1], h3[2], h3[3]);
}

// ============================================================================
// SIMT f32x2 fallback (active only when tcgen05 feature path absent)
// ============================================================================
#define BMF       64
#define BKF       32
#define NTHREADSF 128
#define KTILESF   (DM / BKF)

__device__ __forceinline__ unsigned long long pack2(float a, float b) {
    unsigned long long r;
    asm("mov.b64 %0, {%1, %2};" : "=l"(r) : "f"(a), "f"(b));
    return r;
}
__device__ __forceinline__ void fma2(unsigned long long& d,
                                     unsigned long long a,
                                     unsigned long long b) {
    asm("fma.rn.f32x2 %0, %1, %2, %0;" : "+l"(d) : "l"(a), "l"(b));
}
__device__ __forceinline__ float2 unpack2(unsigned long long v) {
    float2 f;
    asm("mov.b64 {%0, %1}, %2;" : "=f"(f.x), "=f"(f.y) : "l"(v));
    return f;
}

__global__ __launch_bounds__(NTHREADSF)
void router_simt(const float* __restrict__ x,
                 const float* __restrict__ W,
                 const float* __restrict__ b,
                 float* __restrict__ out) {
#if USE_TC
    return;
#else
    __shared__ float xs[BMF][37];
    __shared__ float ws[BKF][66];
    __shared__ float logits[BMF][65];
    __shared__ float bs[NE];

    const int t = threadIdx.x;
    const int tokBase = blockIdx.x * BMF;
    const int lr  = t >> 3;
    const int lkv = (t & 7) * 4;
    const int tm = t & 15;
    const int te = t >> 4;
    const int m0 = tm * 4;
    const int e0 = te * 8;

    if (t < NE) bs[t] = b[t];

    unsigned long long acc[4][4];
#pragma unroll
    for (int i = 0; i < 4; ++i)
#pragma unroll
        for (int p = 0; p < 4; ++p) acc[i][p] = 0ull;

    float4 px[4], pw[4];
#pragma unroll
    for (int p = 0; p < 4; ++p) {
        int r = lr + p * 16;
        px[p] = *(const float4*)(x + (tokBase + r) * DM + lkv);
        pw[p] = *(const float4*)(W + r * DM + lkv);
    }

    for (int it = 0; it < KTILESF; ++it) {
#pragma unroll
        for (int p = 0; p < 4; ++p) {
            int r = lr + p * 16;
            xs[r][lkv + 0] = px[p].x; xs[r][lkv + 1] = px[p].y;
            xs[r][lkv + 2] = px[p].z; xs[r][lkv + 3] = px[p].w;
            ws[lkv + 0][r] = pw[p].x; ws[lkv + 1][r] = pw[p].y;
            ws[lkv + 2][r] = pw[p].z; ws[lkv + 3][r] = pw[p].w;
        }
        __syncthreads();

        if (it + 1 < KTILESF) {
            int k0 = (it + 1) * BKF;
#pragma unroll
            for (int p = 0; p < 4; ++p) {
                int r = lr + p * 16;
                px[p] = *(const float4*)(x + (tokBase + r) * DM + k0 + lkv);
                pw[p] = *(const float4*)(W + r * DM + k0 + lkv);
            }
        }

#pragma unroll 8
        for (int kk = 0; kk < BKF; ++kk) {
            float xv0 = xs[m0 + 0][kk], xv1 = xs[m0 + 1][kk];
            float xv2 = xs[m0 + 2][kk], xv3 = xs[m0 + 3][kk];
            unsigned long long xp[4];
            xp[0] = pack2(xv0, xv0); xp[1] = pack2(xv1, xv1);
            xp[2] = pack2(xv2, xv2); xp[3] = pack2(xv3, xv3);
            const float2* wrow = (const float2*)(&ws[kk][0]);
            unsigned long long wp[4];
#pragma unroll
            for (int p = 0; p < 4; ++p) {
                float2 wv = wrow[(e0 >> 1) + p];
                wp[p] = pack2(wv.x, wv.y);
            }
#pragma unroll
            for (int i = 0; i < 4; ++i)
#pragma unroll
                for (int p = 0; p < 4; ++p) fma2(acc[i][p], xp[i], wp[p]);
        }
        __syncthreads();
    }

#pragma unroll
    for (int i = 0; i < 4; ++i)
#pragma unroll
        for (int p = 0; p < 4; ++p) {
            float2 f = unpack2(acc[i][p]);
            logits[m0 + i][e0 + 2 * p + 0] = f.x;
            logits[m0 + i][e0 + 2 * p + 1] = f.y;
        }
    __syncthreads();

    if (t < BMF) {
        int tok = tokBase + t;
        float m1 = -3.402823466e+38f, m2 = -3.402823466e+38f;
        int i1 = 0, i2 = 0;
#pragma unroll
        for (int e = 0; e < NE; ++e) {
            float v = logits[t][e] + bs[e];
            if (v > m1)      { m2 = m1; i2 = i1; m1 = v; i1 = e; }
            else if (v > m2) { m2 = v;  i2 = e; }
        }
        float sum = 0.0f;
#pragma unroll
        for (int e = 0; e < NE; ++e)
            sum = sum + __expf(logits[t][e] + bs[e] - m1);
        float inv = 1.0f / sum;
        out[tok * 2 + 0] = (float)i1;
        out[tok * 2 + 1] = (float)i2;
        out[TOKENS * 2 + tok * 2 + 0] = inv;
        out[TOKENS * 2 + tok * 2 + 1] = __expf(m2 - m1) * inv;
    }
#endif
}

// ============================================================================
// tcgen05 kernel: round-4 structure (2-stage ring, 1-deep reg prefetch),
// + 6 MMA products, + L2 prefetch of x at distance 3.
// ============================================================================
#define BM     128
#define BK     64
#define NCHUNK (DM / BK)
#define NPROD  512
#define NTHR   544
#define A_SZ   16384
#define B_SZ   8192
#define B_OFF  49152
#define B_BYTES 24576
#define STAGE_SZ 73728
#define SMEM_TOTAL (2048 + 2 * STAGE_SZ)

#define IDESC 0x8100490u   // F32 acc, BF16 a/b, N=64, M=128

#define OFF_TMEM  0
#define OFF_FULL(s) (8  + (s) * 8)
#define OFF_DONE(s) (24 + (s) * 8)
#define OFF_FINAL 40
#define OFF_BIAS  64

#if USE_TC
__device__ __forceinline__ uint32_t smem_u32(const void* p) {
    uint32_t a;
    asm("{ .reg .u64 t; cvta.to.shared.u64 t, %1; cvt.u32.u64 %0, t; }" : "=r"(a) : "l"(p));
    return a;
}
__device__ __forceinline__ bool elect1() {
    uint32_t p;
    asm volatile("{ .reg .pred P; elect.sync _|P, 0xFFFFFFFF; selp.b32 %0, 1, 0, P; }" : "=r"(p));
    return p != 0;
}
#define MBAR_INIT(a, c) asm volatile("mbarrier.init.shared.b64 [%0], %1;" :: "r"(a), "r"(c) : "memory")
#define MBAR_ARRIVE(a)  asm volatile("mbarrier.arrive.shared.b64 _, [%0];" :: "r"(a) : "memory")
#define MBAR_EXPECT(a, n) asm volatile("mbarrier.arrive.expect_tx.shared.b64 _, [%0], %1;" :: "r"(a), "r"(n) : "memory")

__device__ __forceinline__ void mbar_wait(uint32_t mb, uint32_t parity) {
    uint32_t done;
    asm volatile("{ .reg .pred p;\n\t"
        "mbarrier.try_wait.parity.acquire.cta.shared::cta.b64 p, [%1], %2;\n\t"
        "selp.b32 %0, 1, 0, p; }" : "=r"(done) : "r"(mb), "r"(parity) : "memory");
    while (!done) {
        asm volatile("{ .reg .pred p;\n\t"
            "mbarrier.try_wait.parity.acquire.cta.shared::cta.b64 p, [%1], %2, 0x989680;\n\t"
            "selp.b32 %0, 1, 0, p; }" : "=r"(done) : "r"(mb), "r"(parity) : "memory");
    }
}

#define TC_ALLOC(sa, n)  asm volatile("tcgen05.alloc.cta_group::1.sync.aligned.shared::cta.b32 [%0], %1;" :: "r"(sa), "r"(n) : "memory")
#define TC_DEALLOC(t, n) asm volatile("tcgen05.dealloc.cta_group::1.sync.aligned.b32 %0, %1;" :: "r"(t), "r"(n))
#define TC_RELINQ()      asm volatile("tcgen05.relinquish_alloc_permit.cta_group::1.sync.aligned;")
#define TC_COMMIT(mb)    asm volatile("tcgen05.commit.cta_group::1.mbarrier::arrive::one.shared::cluster.b64 [%0];" :: "r"(mb) : "memory")
#define TC_FENCE_AFTER() asm volatile("tcgen05.fence::after_thread_sync;" ::: "memory")
#define TC_WAIT_LD()     asm volatile("tcgen05.wait::ld.sync.aligned;" ::: "memory")
#define FENCE_ASYNC()    asm volatile("fence.proxy.async.shared::cta;" ::: "memory")

__device__ __forceinline__ void bulk_g2s(uint32_t dst, const void* src,
                                         uint32_t bytes, uint32_t mbar) {
    asm volatile("cp.async.bulk.shared::cluster.global.mbarrier::complete_tx::bytes "
                 "[%0], [%1], %2, [%3];"
                 :: "r"(dst), "l"(src), "r"(bytes), "r"(mbar) : "memory");
}

__device__ __forceinline__ void tcmma(uint32_t d, uint64_t ad, uint64_t bd, uint32_t en) {
    asm volatile("{ .reg .pred p;\n\t"
        "setp.ne.u32 p, %4, 0;\n\t"
        "tcgen05.mma.cta_group::1.kind::f16 [%0], %1, %2, %3, {%5,%5,%5,%5}, p; }"
        :: "r"(d), "l"(ad), "l"(bd), "r"(IDESC), "r"(en), "r"(0u) : "memory");
}

#define LDTM32(r, addr) \
    asm volatile("tcgen05.ld.sync.aligned.32x32b.x32.b32 " \
        "{%0,%1,%2,%3,%4,%5,%6,%7,%8,%9,%10,%11,%12,%13,%14,%15," \
        "%16,%17,%18,%19,%20,%21,%22,%23,%24,%25,%26,%27,%28,%29,%30,%31}, [%32];" \
        : "=r"((r)[0]),"=r"((r)[1]),"=r"((r)[2]),"=r"((r)[3]),"=r"((r)[4]),"=r"((r)[5]),"=r"((r)[6]),"=r"((r)[7]), \
          "=r"((r)[8]),"=r"((r)[9]),"=r"((r)[10]),"=r"((r)[11]),"=r"((r)[12]),"=r"((r)[13]),"=r"((r)[14]),"=r"((r)[15]), \
          "=r"((r)[16]),"=r"((r)[17]),"=r"((r)[18]),"=r"((r)[19]),"=r"((r)[20]),"=r"((r)[21]),"=r"((r)[22]),"=r"((r)[23]), \
          "=r"((r)[24]),"=r"((r)[25]),"=r"((r)[26]),"=r"((r)[27]),"=r"((r)[28]),"=r"((r)[29]),"=r"((r)[30]),"=r"((r)[31]) \
        : "r"(addr))

__device__ __forceinline__ void cvt_store8(float4 va, float4 vb, uint32_t base,
                                           uint32_t sstride, uint32_t off) {
    uint32_t sw = base + (off ^ ((off >> 3) & 0x70));
    uint32_t h1[4], h2[4], h3[4];
    split8(va, vb, h1, h2, h3);
    asm volatile("st.shared.v4.b32 [%0], {%1,%2,%3,%4};"
                 :: "r"(sw), "r"(h1[0]), "r"(h1[1]), "r"(h1[2]), "r"(h1[3]));
    asm volatile("st.shared.v4.b32 [%0], {%1,%2,%3,%4};"
                 :: "r"(sw + sstride), "r"(h2[0]), "r"(h2[1]), "r"(h2[2]), "r"(h2[3]));
    asm volatile("st.shared.v4.b32 [%0], {%1,%2,%3,%4};"
                 :: "r"(sw + 2 * sstride), "r"(h3[0]), "r"(h3[1]), "r"(h3[2]), "r"(h3[3]));
}
#endif  // USE_TC

__global__ void __launch_bounds__(NTHR, 1)
router_tc(const float* __restrict__ x, const float* __restrict__ b,
          float* __restrict__ out) {
#if USE_TC
    extern __shared__ char smem[];
    const uint32_t sb = smem_u32(smem);
    const uint32_t ab = (sb + 2047) & ~1023u;
    const int t = threadIdx.x;

    if (t == 0) {
        MBAR_INIT(sb + OFF_FULL(0), 2); MBAR_INIT(sb + OFF_FULL(1), 2);
        MBAR_INIT(sb + OFF_DONE(0), 1); MBAR_INIT(sb + OFF_DONE(1), 1);
        MBAR_INIT(sb + OFF_FINAL, 1);
    }
    if (t < NE) *(float*)(smem + OFF_BIAS + t * 4) = b[t];
    if (t >= NPROD) {
        TC_ALLOC(sb + OFF_TMEM, 128);
    }
    __syncthreads();
    uint32_t tmem;
    asm volatile("ld.shared.b32 %0, [%1];" : "=r"(tmem) : "r"(sb + OFF_TMEM));

    if (t >= NPROD) {
        // ---- MMA warp ----
        const uint64_t DB = (2ULL << 61) | (1ULL << 46) | (64ULL << 32) | (1ULL << 16);
        uint64_t ad[2][3], bd[2][3];
#pragma unroll
        for (int s = 0; s < 2; ++s)
#pragma unroll
            for (int sp = 0; sp < 3; ++sp) {
                ad[s][sp] = DB | (((ab + s * STAGE_SZ + sp * A_SZ) >> 4) & 0x3FFF);
                bd[s][sp] = DB | (((ab + s * STAGE_SZ + B_OFF + sp * B_SZ) >> 4) & 0x3FFF);
            }
        for (int i = 0; i < NCHUNK; ++i) {
            const int s = i & 1;
            mbar_wait(sb + OFF_FULL(s), (i >> 1) & 1);
            if (elect1()) {
#pragma unroll
                for (int ks = 0; ks < 4; ++ks) {
                    uint32_t en0 = (i > 0 || ks > 0) ? 1u : 0u;
                    uint64_t ko = (uint64_t)(ks * 2);
                    tcmma(tmem, ad[s][0] + ko, bd[s][0] + ko, en0);  // x1w1
                    tcmma(tmem, ad[s][0] + ko, bd[s][1] + ko, 1u);   // x1w2
                    tcmma(tmem, ad[s][1] + ko, bd[s][0] + ko, 1u);   // x2w1
                    tcmma(tmem, ad[s][1] + ko, bd[s][1] + ko, 1u);   // x2w2
                    tcmma(tmem, ad[s][0] + ko, bd[s][2] + ko, 1u);   // x1w3
                    tcmma(tmem, ad[s][2] + ko, bd[s][0] + ko, 1u);   // x3w1
                }
                TC_COMMIT(sb + OFF_DONE(s));
            }
        }
        if (elect1()) TC_COMMIT(sb + OFF_FINAL);
    } else {
        // ---- producers: x conversion + B bulk copy ----
        const int row  = t >> 2;            // token row 0..127
        const int colf = (t & 3) * 16;      // 16 floats per thread
        const float* xp = x + (size_t)(blockIdx.x * BM + row) * DM + colf;
        float4 bx[4];
#pragma unroll
        for (int j = 0; j < 4; ++j) bx[j] = ((const float4*)xp)[j];
        // warm L2 for the next couple of chunks
        asm volatile("prefetch.global.L2 [%0];" :: "l"(xp + BK) : "memory");
        asm volatile("prefetch.global.L2 [%0];" :: "l"(xp + 2 * BK) : "memory");

        int done_ph0 = 0, done_ph1 = 0;
        for (int i = 0; i < NCHUNK; ++i) {
            const int s = i & 1;
            if (i >= 2) {
                if (s == 0) { mbar_wait(sb + OFF_DONE(0), done_ph0); done_ph0 ^= 1; }
                else        { mbar_wait(sb + OFF_DONE(1), done_ph1); done_ph1 ^= 1; }
            }
            // L2 prefetch for chunk i+3 (issued before the conversion work)
            if (i + 3 < NCHUNK) {
                asm volatile("prefetch.global.L2 [%0];"
                             :: "l"(xp + (i + 3) * BK) : "memory");
            }
            const uint32_t abase = ab + s * STAGE_SZ;
            if (t == 0) {
                MBAR_EXPECT(sb + OFF_FULL(s), B_BYTES);
                bulk_g2s(abase + B_OFF, g_wb + (size_t)i * B_BYTES, B_BYTES,
                         sb + OFF_FULL(s));
            }
#pragma unroll
            for (int g = 0; g < 2; ++g)
                cvt_store8(bx[2 * g], bx[2 * g + 1], abase, A_SZ,
                           (uint32_t)(row * 128 + colf * 2 + g * 16));
            if (i + 1 < NCHUNK) {
                const float4* xn = (const float4*)(xp + (i + 1) * BK);
#pragma unroll
                for (int j = 0; j < 4; ++j) bx[j] = xn[j];
            }
            FENCE_ASYNC();
            asm volatile("bar.sync 1, 512;" ::: "memory");
            if (t == 0) MBAR_ARRIVE(sb + OFF_FULL(s));
        }
    }

    // ---- epilogue: warps 0-3 read TMEM, bias + top-2 + softmax ----
    if (t < 128) {
        mbar_wait(sb + OFF_FINAL, 0);
        TC_FENCE_AFTER();
        uint32_t d0[32], d1[32];
        LDTM32(d0, tmem);
        LDTM32(d1, tmem + 32);
        TC_WAIT_LD();

        float vv[64];
#pragma unroll
        for (int e = 0; e < 32; ++e)
            vv[e] = __uint_as_float(d0[e]) + *(const float*)(smem + OFF_BIAS + e * 4);
#pragma unroll
        for (int e = 0; e < 32; ++e)
            vv[32 + e] = __uint_as_float(d1[e]) + *(const float*)(smem + OFF_BIAS + (32 + e) * 4);

        float m1 = -3.402823466e38f, m2 = -3.402823466e38f;
        int i1 = 0, i2 = 0;
#pragma unroll
        for (int e = 0; e < 64; ++e) {
            float v = vv[e];
            if (v > m1)      { m2 = m1; i2 = i1; m1 = v; i1 = e; }
            else if (v > m2) { m2 = v;  i2 = e; }
        }
        float sum = 0.0f;
#pragma unroll
        for (int e = 0; e < 64; ++e) sum += __expf(vv[e] - m1);
        float inv = 1.0f / sum;

        int tok = blockIdx.x * BM + t;
        out[tok * 2 + 0] = (float)i1;
        out[tok * 2 + 1] = (float)i2;
        out[TOKENS * 2 + tok * 2 + 0] = inv;
        out[TOKENS * 2 + tok * 2 + 1] = __expf(m2 - m1) * inv;
    }

    __syncthreads();
    if (t >= NPROD) {
        TC_RELINQ();
        TC_DEALLOC(tmem, 128);
    }
#endif  // USE_TC
}

// ============================================================================
extern "C" void kernel_launch(void* const* d_in, const int* in_sizes, int n_in,
                              void* d_out, int out_size) {
    const float* x = (const float*)d_in[0];
    const float* W = (const float*)d_in[1];
    const float* b = (const float*)d_in[2];
    float* out = (float*)d_out;
    (void)in_sizes; (void)n_in; (void)out_size;

    wsplit_kernel<<<128, 256>>>(W);

    router_simt<<<TOKENS / BMF, NTHREADSF>>>(x, W, b, out);

    cudaFuncSetAttribute(router_tc, cudaFuncAttributeMaxDynamicSharedMemorySize, SMEM_TOTAL);
    router_tc<<<TOKENS / BM, NTHR, SMEM_TOTAL>>>(x, b, out);
}

// round 10
// speedup vs baseline: 2.0819x; 1.0338x over previous
#include <cuda_runtime.h>
#include <cstdint>

#if defined(__CUDA_ARCH__) && defined(__CUDA_ARCH_FEAT_SM103_ALL)
#define USE_TC 1
#else
#define USE_TC 0
#endif

#define TOKENS 16384
#define DM     4096
#define NE     64

// ============================================================================
// W pre-split: 3-way exact bf16 split of W -> swizzled B-tile images.
// ============================================================================
__device__ __align__(16) unsigned char g_wb[64 * 24576];

__device__ __forceinline__ void split8(const float4 va, const float4 vb,
                                       uint32_t* h1, uint32_t* h2, uint32_t* h3) {
    float f[8] = {va.x, va.y, va.z, va.w, vb.x, vb.y, vb.z, vb.w};
#pragma unroll
    for (int p = 0; p < 4; ++p) {
        float a = f[2 * p], c = f[2 * p + 1];
        uint32_t ua = __float_as_uint(a), uc = __float_as_uint(c);
        h1[p] = __byte_perm(ua, uc, 0x7632);
        float r1a = a - __uint_as_float(ua & 0xffff0000u);
        float r1c = c - __uint_as_float(uc & 0xffff0000u);
        uint32_t ra = __float_as_uint(r1a), rc = __float_as_uint(r1c);
        h2[p] = __byte_perm(ra, rc, 0x7632);
        float r2a = r1a - __uint_as_float(ra & 0xffff0000u);
        float r2c = r1c - __uint_as_float(rc & 0xffff0000u);
        asm("cvt.rn.bf16x2.f32 %0, %1, %2;" : "=r"(h3[p]) : "f"(r2c), "f"(r2a));
    }
}

// split one float4 -> 2 b32 per split tier
__device__ __forceinline__ void split4(const float4 v,
                                       uint32_t* h1, uint32_t* h2, uint32_t* h3) {
    float f[4] = {v.x, v.y, v.z, v.w};
#pragma unroll
    for (int p = 0; p < 2; ++p) {
        float a = f[2 * p], c = f[2 * p + 1];
        uint32_t ua = __float_as_uint(a), uc = __float_as_uint(c);
        h1[p] = __byte_perm(ua, uc, 0x7632);
        float r1a = a - __uint_as_float(ua & 0xffff0000u);
        float r1c = c - __uint_as_float(uc & 0xffff0000u);
        uint32_t ra = __float_as_uint(r1a), rc = __float_as_uint(r1c);
        h2[p] = __byte_perm(ra, rc, 0x7632);
        float r2a = r1a - __uint_as_float(ra & 0xffff0000u);
        float r2c = r1c - __uint_as_float(rc & 0xffff0000u);
        asm("cvt.rn.bf16x2.f32 %0, %1, %2;" : "=r"(h3[p]) : "f"(r2c), "f"(r2a));
    }
}

__global__ __launch_bounds__(256)
void wsplit_kernel(const float* __restrict__ W) {
    const int c = blockIdx.x >> 1;
    const int h = blockIdx.x & 1;
    const int t = threadIdx.x;
    const int e  = h * 32 + (t >> 3);
    const int fg = (t & 7) * 8;
    const float4* src = (const float4*)(W + (size_t)e * DM + c * 64 + fg);
    unsigned char* dst = g_wb + (size_t)c * 24576;
    uint32_t h1[4], h2[4], h3[4];
    split8(src[0], src[1], h1, h2, h3);
    uint32_t off = (uint32_t)(e * 128 + fg * 2);
    uint32_t sw = off ^ ((off >> 3) & 0x70);
    *(uint4*)(dst + sw)         = make_uint4(h1[0], h1[1], h1[2], h1[3]);
    *(uint4*)(dst + 8192 + sw)  = make_uint4(h2[0], h2[1], h2[2], h2[3]);
    *(uint4*)(dst + 16384 + sw) = make_uint4(h3[0], h3[1], h3[2], h3[3]);
}

// ============================================================================
// SIMT f32x2 fallback (active only when tcgen05 feature path absent)
// ============================================================================
#define BMF       64
#define BKF       32
#define NTHREADSF 128
#define KTILESF   (DM / BKF)

__device__ __forceinline__ unsigned long long pack2(float a, float b) {
    unsigned long long r;
    asm("mov.b64 %0, {%1, %2};" : "=l"(r) : "f"(a), "f"(b));
    return r;
}
__device__ __forceinline__ void fma2(unsigned long long& d,
                                     unsigned long long a,
                                     unsigned long long b) {
    asm("fma.rn.f32x2 %0, %1, %2, %0;" : "+l"(d) : "l"(a), "l"(b));
}
__device__ __forceinline__ float2 unpack2(unsigned long long v) {
    float2 f;
    asm("mov.b64 {%0, %1}, %2;" : "=f"(f.x), "=f"(f.y) : "l"(v));
    return f;
}

__global__ __launch_bounds__(NTHREADSF)
void router_simt(const float* __restrict__ x,
                 const float* __restrict__ W,
                 const float* __restrict__ b,
                 float* __restrict__ out) {
#if USE_TC
    return;
#else
    __shared__ float xs[BMF][37];
    __shared__ float ws[BKF][66];
    __shared__ float logits[BMF][65];
    __shared__ float bs[NE];

    const int t = threadIdx.x;
    const int tokBase = blockIdx.x * BMF;
    const int lr  = t >> 3;
    const int lkv = (t & 7) * 4;
    const int tm = t & 15;
    const int te = t >> 4;
    const int m0 = tm * 4;
    const int e0 = te * 8;

    if (t < NE) bs[t] = b[t];

    unsigned long long acc[4][4];
#pragma unroll
    for (int i = 0; i < 4; ++i)
#pragma unroll
        for (int p = 0; p < 4; ++p) acc[i][p] = 0ull;

    float4 px[4], pw[4];
#pragma unroll
    for (int p = 0; p < 4; ++p) {
        int r = lr + p * 16;
        px[p] = *(const float4*)(x + (tokBase + r) * DM + lkv);
        pw[p] = *(const float4*)(W + r * DM + lkv);
    }

    for (int it = 0; it < KTILESF; ++it) {
#pragma unroll
        for (int p = 0; p < 4; ++p) {
            int r = lr + p * 16;
            xs[r][lkv + 0] = px[p].x; xs[r][lkv + 1] = px[p].y;
            xs[r][lkv + 2] = px[p].z; xs[r][lkv + 3] = px[p].w;
            ws[lkv + 0][r] = pw[p].x; ws[lkv + 1][r] = pw[p].y;
            ws[lkv + 2][r] = pw[p].z; ws[lkv + 3][r] = pw[p].w;
        }
        __syncthreads();

        if (it + 1 < KTILESF) {
            int k0 = (it + 1) * BKF;
#pragma unroll
            for (int p = 0; p < 4; ++p) {
                int r = lr + p * 16;
                px[p] = *(const float4*)(x + (tokBase + r) * DM + k0 + lkv);
                pw[p] = *(const float4*)(W + r * DM + k0 + lkv);
            }
        }

#pragma unroll 8
        for (int kk = 0; kk < BKF; ++kk) {
            float xv0 = xs[m0 + 0][kk], xv1 = xs[m0 + 1][kk];
            float xv2 = xs[m0 + 2][kk], xv3 = xs[m0 + 3][kk];
            unsigned long long xp[4];
            xp[0] = pack2(xv0, xv0); xp[1] = pack2(xv1, xv1);
            xp[2] = pack2(xv2, xv2); xp[3] = pack2(xv3, xv3);
            const float2* wrow = (const float2*)(&ws[kk][0]);
            unsigned long long wp[4];
#pragma unroll
            for (int p = 0; p < 4; ++p) {
                float2 wv = wrow[(e0 >> 1) + p];
                wp[p] = pack2(wv.x, wv.y);
            }
#pragma unroll
            for (int i = 0; i < 4; ++i)
#pragma unroll
                for (int p = 0; p < 4; ++p) fma2(acc[i][p], xp[i], wp[p]);
        }
        __syncthreads();
    }

#pragma unroll
    for (int i = 0; i < 4; ++i)
#pragma unroll
        for (int p = 0; p < 4; ++p) {
            float2 f = unpack2(acc[i][p]);
            logits[m0 + i][e0 + 2 * p + 0] = f.x;
            logits[m0 + i][e0 + 2 * p + 1] = f.y;
        }
    __syncthreads();

    if (t < BMF) {
        int tok = tokBase + t;
        float m1 = -3.402823466e+38f, m2 = -3.402823466e+38f;
        int i1 = 0, i2 = 0;
#pragma unroll
        for (int e = 0; e < NE; ++e) {
            float v = logits[t][e] + bs[e];
            if (v > m1)      { m2 = m1; i2 = i1; m1 = v; i1 = e; }
            else if (v > m2) { m2 = v;  i2 = e; }
        }
        float sum = 0.0f;
#pragma unroll
        for (int e = 0; e < NE; ++e)
            sum = sum + __expf(logits[t][e] + bs[e] - m1);
        float inv = 1.0f / sum;
        out[tok * 2 + 0] = (float)i1;
        out[tok * 2 + 1] = (float)i2;
        out[TOKENS * 2 + tok * 2 + 0] = inv;
        out[TOKENS * 2 + tok * 2 + 1] = __expf(m2 - m1) * inv;
    }
#endif
}

// ============================================================================
// tcgen05 kernel: coalesced x-LDG remap + per-warp arrives (no bar.sync)
// ============================================================================
#define BM     128
#define BK     64
#define NCHUNK (DM / BK)
#define NPROD  512
#define NTHR   544
#define A_SZ   16384
#define B_SZ   8192
#define B_OFF  49152
#define B_BYTES 24576
#define STAGE_SZ 73728
#define SMEM_TOTAL (2048 + 2 * STAGE_SZ)

#define IDESC 0x8100490u   // F32 acc, BF16 a/b, N=64, M=128

#define OFF_TMEM  0
#define OFF_FULL(s) (8  + (s) * 8)
#define OFF_DONE(s) (24 + (s) * 8)
#define OFF_FINAL 40
#define OFF_BIAS  64

#if USE_TC
__device__ __forceinline__ uint32_t smem_u32(const void* p) {
    uint32_t a;
    asm("{ .reg .u64 t; cvta.to.shared.u64 t, %1; cvt.u32.u64 %0, t; }" : "=r"(a) : "l"(p));
    return a;
}
__device__ __forceinline__ bool elect1() {
    uint32_t p;
    asm volatile("{ .reg .pred P; elect.sync _|P, 0xFFFFFFFF; selp.b32 %0, 1, 0, P; }" : "=r"(p));
    return p != 0;
}
#define MBAR_INIT(a, c) asm volatile("mbarrier.init.shared.b64 [%0], %1;" :: "r"(a), "r"(c) : "memory")
#define MBAR_ARRIVE(a)  asm volatile("mbarrier.arrive.shared.b64 _, [%0];" :: "r"(a) : "memory")
#define MBAR_EXPECT(a, n) asm volatile("mbarrier.arrive.expect_tx.shared.b64 _, [%0], %1;" :: "r"(a), "r"(n) : "memory")

__device__ __forceinline__ void mbar_wait(uint32_t mb, uint32_t parity) {
    uint32_t done;
    asm volatile("{ .reg .pred p;\n\t"
        "mbarrier.try_wait.parity.acquire.cta.shared::cta.b64 p, [%1], %2;\n\t"
        "selp.b32 %0, 1, 0, p; }" : "=r"(done) : "r"(mb), "r"(parity) : "memory");
    while (!done) {
        asm volatile("{ .reg .pred p;\n\t"
            "mbarrier.try_wait.parity.acquire.cta.shared::cta.b64 p, [%1], %2, 0x989680;\n\t"
            "selp.b32 %0, 1, 0, p; }" : "=r"(done) : "r"(mb), "r"(parity) : "memory");
    }
}

#define TC_ALLOC(sa, n)  asm volatile("tcgen05.alloc.cta_group::1.sync.aligned.shared::cta.b32 [%0], %1;" :: "r"(sa), "r"(n) : "memory")
#define TC_DEALLOC(t, n) asm volatile("tcgen05.dealloc.cta_group::1.sync.aligned.b32 %0, %1;" :: "r"(t), "r"(n))
#define TC_RELINQ()      asm volatile("tcgen05.relinquish_alloc_permit.cta_group::1.sync.aligned;")
#define TC_COMMIT(mb)    asm volatile("tcgen05.commit.cta_group::1.mbarrier::arrive::one.shared::cluster.b64 [%0];" :: "r"(mb) : "memory")
#define TC_FENCE_AFTER() asm volatile("tcgen05.fence::after_thread_sync;" ::: "memory")
#define TC_WAIT_LD()     asm volatile("tcgen05.wait::ld.sync.aligned;" ::: "memory")
#define FENCE_ASYNC()    asm volatile("fence.proxy.async.shared::cta;" ::: "memory")

__device__ __forceinline__ void bulk_g2s(uint32_t dst, const void* src,
                                         uint32_t bytes, uint32_t mbar) {
    asm volatile("cp.async.bulk.shared::cluster.global.mbarrier::complete_tx::bytes "
                 "[%0], [%1], %2, [%3];"
                 :: "r"(dst), "l"(src), "r"(bytes), "r"(mbar) : "memory");
}

__device__ __forceinline__ void tcmma(uint32_t d, uint64_t ad, uint64_t bd, uint32_t en) {
    asm volatile("{ .reg .pred p;\n\t"
        "setp.ne.u32 p, %4, 0;\n\t"
        "tcgen05.mma.cta_group::1.kind::f16 [%0], %1, %2, %3, {%5,%5,%5,%5}, p; }"
        :: "r"(d), "l"(ad), "l"(bd), "r"(IDESC), "r"(en), "r"(0u) : "memory");
}

#define LDTM32(r, addr) \
    asm volatile("tcgen05.ld.sync.aligned.32x32b.x32.b32 " \
        "{%0,%1,%2,%3,%4,%5,%6,%7,%8,%9,%10,%11,%12,%13,%14,%15," \
        "%16,%17,%18,%19,%20,%21,%22,%23,%24,%25,%26,%27,%28,%29,%30,%31}, [%32];" \
        : "=r"((r)[0]),"=r"((r)[1]),"=r"((r)[2]),"=r"((r)[3]),"=r"((r)[4]),"=r"((r)[5]),"=r"((r)[6]),"=r"((r)[7]), \
          "=r"((r)[8]),"=r"((r)[9]),"=r"((r)[10]),"=r"((r)[11]),"=r"((r)[12]),"=r"((r)[13]),"=r"((r)[14]),"=r"((r)[15]), \
          "=r"((r)[16]),"=r"((r)[17]),"=r"((r)[18]),"=r"((r)[19]),"=r"((r)[20]),"=r"((r)[21]),"=r"((r)[22]),"=r"((r)[23]), \
          "=r"((r)[24]),"=r"((r)[25]),"=r"((r)[26]),"=r"((r)[27]),"=r"((r)[28]),"=r"((r)[29]),"=r"((r)[30]),"=r"((r)[31]) \
        : "r"(addr))
#endif  // USE_TC

__global__ void __launch_bounds__(NTHR, 1)
router_tc(const float* __restrict__ x, const float* __restrict__ b,
          float* __restrict__ out) {
#if USE_TC
    extern __shared__ char smem[];
    const uint32_t sb = smem_u32(smem);
    const uint32_t ab = (sb + 2047) & ~1023u;
    const int t = threadIdx.x;

    if (t == 0) {
        // full: 16 producer-warp arrives + 1 expect_tx arrive (t0) = 17
        MBAR_INIT(sb + OFF_FULL(0), 17); MBAR_INIT(sb + OFF_FULL(1), 17);
        MBAR_INIT(sb + OFF_DONE(0), 1);  MBAR_INIT(sb + OFF_DONE(1), 1);
        MBAR_INIT(sb + OFF_FINAL, 1);
    }
    if (t < NE) *(float*)(smem + OFF_BIAS + t * 4) = b[t];
    if (t >= NPROD) {
        TC_ALLOC(sb + OFF_TMEM, 128);
    }
    __syncthreads();
    uint32_t tmem;
    asm volatile("ld.shared.b32 %0, [%1];" : "=r"(tmem) : "r"(sb + OFF_TMEM));

    if (t >= NPROD) {
        // ---- MMA warp ----
        const uint64_t DB = (2ULL << 61) | (1ULL << 46) | (64ULL << 32) | (1ULL << 16);
        uint64_t ad[2][3], bd[2][3];
#pragma unroll
        for (int s = 0; s < 2; ++s)
#pragma unroll
            for (int sp = 0; sp < 3; ++sp) {
                ad[s][sp] = DB | (((ab + s * STAGE_SZ + sp * A_SZ) >> 4) & 0x3FFF);
                bd[s][sp] = DB | (((ab + s * STAGE_SZ + B_OFF + sp * B_SZ) >> 4) & 0x3FFF);
            }
        for (int i = 0; i < NCHUNK; ++i) {
            const int s = i & 1;
            mbar_wait(sb + OFF_FULL(s), (i >> 1) & 1);
            if (elect1()) {
#pragma unroll
                for (int ks = 0; ks < 4; ++ks) {
                    uint32_t en0 = (i > 0 || ks > 0) ? 1u : 0u;
                    uint64_t ko = (uint64_t)(ks * 2);
                    tcmma(tmem, ad[s][0] + ko, bd[s][0] + ko, en0);  // x1w1
                    tcmma(tmem, ad[s][0] + ko, bd[s][1] + ko, 1u);   // x1w2
                    tcmma(tmem, ad[s][1] + ko, bd[s][0] + ko, 1u);   // x2w1
                    tcmma(tmem, ad[s][1] + ko, bd[s][1] + ko, 1u);   // x2w2
                    tcmma(tmem, ad[s][0] + ko, bd[s][2] + ko, 1u);   // x1w3
                    tcmma(tmem, ad[s][2] + ko, bd[s][0] + ko, 1u);   // x3w1
                }
                TC_COMMIT(sb + OFF_DONE(s));
            }
        }
        if (elect1()) TC_COMMIT(sb + OFF_FINAL);
    } else {
        // ---- producers: coalesced x loads + convert + B bulk copy ----
        const int w    = t >> 5;            // producer warp 0..15
        const int lane = t & 31;
        const int sub  = lane >> 4;         // 0/1: which row of the pair
        const int fc   = (lane & 15) * 4;   // float index within row (0..60)
        const int rbase = 8 * w;            // rows 8w..8w+7
        const int tokBase = blockIdx.x * BM;

        // per-thread rows: r_k = rbase + 2k + sub (k=0..3)
        const float* gp[4];
#pragma unroll
        for (int k = 0; k < 4; ++k)
            gp[k] = x + (size_t)(tokBase + rbase + 2 * k + sub) * DM + fc;

        float4 bx[4];
#pragma unroll
        for (int k = 0; k < 4; ++k) bx[k] = *(const float4*)gp[k];

        // L2 warm for chunks 1,2: lanes 0-15 each prefetch one 128B line
        if (lane < 16) {
            const float* pr = x + (size_t)(tokBase + rbase + (lane >> 1)) * DM
                              + (lane & 1) * 32;
            asm volatile("prefetch.global.L2 [%0];" :: "l"(pr + BK) : "memory");
            asm volatile("prefetch.global.L2 [%0];" :: "l"(pr + 2 * BK) : "memory");
        }

        int done_ph0 = 0, done_ph1 = 0;
        for (int i = 0; i < NCHUNK; ++i) {
            const int s = i & 1;
            if (i >= 2) {
                if (s == 0) { mbar_wait(sb + OFF_DONE(0), done_ph0); done_ph0 ^= 1; }
                else        { mbar_wait(sb + OFF_DONE(1), done_ph1); done_ph1 ^= 1; }
            }
            if (i + 3 < NCHUNK && lane < 16) {
                const float* pr = x + (size_t)(tokBase + rbase + (lane >> 1)) * DM
                                  + (i + 3) * BK + (lane & 1) * 32;
                asm volatile("prefetch.global.L2 [%0];" :: "l"(pr) : "memory");
            }
            const uint32_t abase = ab + s * STAGE_SZ;
            if (t == 0) {
                MBAR_EXPECT(sb + OFF_FULL(s), B_BYTES);
                bulk_g2s(abase + B_OFF, g_wb + (size_t)i * B_BYTES, B_BYTES,
                         sb + OFF_FULL(s));
            }
            // convert + store: 4 rows x (h1,h2,h3) 8B each
#pragma unroll
            for (int k = 0; k < 4; ++k) {
                uint32_t h1[2], h2[2], h3[2];
                split4(bx[k], h1, h2, h3);
                uint32_t off = (uint32_t)((rbase + 2 * k + sub) * 128 + fc * 2);
                uint32_t sw = abase + (off ^ ((off >> 3) & 0x70));
                asm volatile("st.shared.v2.b32 [%0], {%1,%2};"
                             :: "r"(sw), "r"(h1[0]), "r"(h1[1]));
                asm volatile("st.shared.v2.b32 [%0], {%1,%2};"
                             :: "r"(sw + A_SZ), "r"(h2[0]), "r"(h2[1]));
                asm volatile("st.shared.v2.b32 [%0], {%1,%2};"
                             :: "r"(sw + 2 * A_SZ), "r"(h3[0]), "r"(h3[1]));
            }
            // load next chunk
            if (i + 1 < NCHUNK) {
#pragma unroll
                for (int k = 0; k < 4; ++k)
                    bx[k] = *(const float4*)(gp[k] + (i + 1) * BK);
            }
            FENCE_ASYNC();
            __syncwarp();
            if (lane == 0) MBAR_ARRIVE(sb + OFF_FULL(s));
        }
    }

    // ---- epilogue: warps 0-3 read TMEM, bias + top-2 + softmax ----
    if (t < 128) {
        mbar_wait(sb + OFF_FINAL, 0);
        TC_FENCE_AFTER();
        uint32_t d0[32], d1[32];
        LDTM32(d0, tmem);
        LDTM32(d1, tmem + 32);
        TC_WAIT_LD();

        float vv[64];
#pragma unroll
        for (int e = 0; e < 32; ++e)
            vv[e] = __uint_as_float(d0[e]) + *(const float*)(smem + OFF_BIAS + e * 4);
#pragma unroll
        for (int e = 0; e < 32; ++e)
            vv[32 + e] = __uint_as_float(d1[e]) + *(const float*)(smem + OFF_BIAS + (32 + e) * 4);

        float m1 = -3.402823466e38f, m2 = -3.402823466e38f;
        int i1 = 0, i2 = 0;
#pragma unroll
        for (int e = 0; e < 64; ++e) {
            float v = vv[e];
            if (v > m1)      { m2 = m1; i2 = i1; m1 = v; i1 = e; }
            else if (v > m2) { m2 = v;  i2 = e; }
        }
        float sum = 0.0f;
#pragma unroll
        for (int e = 0; e < 64; ++e) sum += __expf(vv[e] - m1);
        float inv = 1.0f / sum;

        int tok = blockIdx.x * BM + t;
        out[tok * 2 + 0] = (float)i1;
        out[tok * 2 + 1] = (float)i2;
        out[TOKENS * 2 + tok * 2 + 0] = inv;
        out[TOKENS * 2 + tok * 2 + 1] = __expf(m2 - m1) * inv;
    }

    __syncthreads();
    if (t >= NPROD) {
        TC_RELINQ();
        TC_DEALLOC(tmem, 128);
    }
#endif  // USE_TC
}

// ============================================================================
extern "C" void kernel_launch(void* const* d_in, const int* in_sizes, int n_in,
                              void* d_out, int out_size) {
    const float* x = (const float*)d_in[0];
    const float* W = (const float*)d_in[1];
    const float* b = (const float*)d_in[2];
    float* out = (float*)d_out;
    (void)in_sizes; (void)n_in; (void)out_size;

    wsplit_kernel<<<128, 256>>>(W);

    router_simt<<<TOKENS / BMF, NTHREADSF>>>(x, W, b, out);

    cudaFuncSetAttribute(router_tc, cudaFuncAttributeMaxDynamicSharedMemorySize, SMEM_TOTAL);
    router_tc<<<TOKENS / BM, NTHR, SMEM_TOTAL>>>(x, b, out);
}